// round 11
// baseline (speedup 1.0000x reference)
#include <cuda_runtime.h>
#include <math.h>
#include <stdint.h>
#include <cuda_bf16.h>

#define NN   8192      // nodes per graph side (B*S)
#define FD   256       // hidden dim
#define FIN0 512       // input dim
#define NE   65536     // directed edges per graph (already symmetric)
#define NB   256       // batch
#define SS   32        // nodes per graph
#define LLY  3         // layers
#define NG   (2 * NB)  // total graphs (q side then c side)
#define FP   (FD / 2)  // bf16 pairs per feature row (128)
#define XW   (FIN0 / 2)// bf16 pairs per input row (256)

// dynamic smem layout (words): As[3][128][20] then Bs[3][16][132]
#define AS_STRIDE 20
#define BS_STRIDE 132
#define AS_STAGE  (128 * AS_STRIDE)            // 2560 words
#define BS_BASE   (3 * AS_STAGE)               // 7680 words
#define BS_STAGE  (16 * BS_STRIDE)             // 2112 words
#define DSM_BYTES ((BS_BASE + 3 * BS_STAGE) * 4)   // 56064 bytes

// ---------------- scratch (static device globals; no allocation) -------------
__device__ int      g_adjcnt[NG * SS * SS];
__device__ uint32_t g_adjP[NG * SS * 16];            // normalized adjacency bf16x2
__device__ uint32_t g_xb[2 * NN * XW];               // input x as bf16 pairs
__device__ uint32_t g_wb0[(FIN0 / 2) * FD];          // W0 packed (k,k+1) pairs
__device__ uint32_t g_wb1[(FD / 2) * FD];
__device__ uint32_t g_wb2[(FD / 2) * FD];
__device__ uint32_t g_featb[LLY * 2 * NN * FP];      // pre-ReLU features (bf16)
__device__ uint32_t g_featr[2 * 2 * NN * FP];        // post-ReLU features (bf16)
__device__ float    g_mcost[NB * LLY];

// ---------------- helpers ----------------------------------------------------
__device__ __forceinline__ uint32_t pack_bf16x2(float lo, float hi) {
    uint32_t r;
    asm("cvt.rn.bf16x2.f32 %0, %1, %2;" : "=r"(r) : "f"(hi), "f"(lo));
    return r;
}
__device__ __forceinline__ void mma16(float* c, const uint32_t* a,
                                      uint32_t b0, uint32_t b1) {
    asm volatile("mma.sync.aligned.m16n8k16.row.col.f32.bf16.bf16.f32 "
                 "{%0,%1,%2,%3}, {%4,%5,%6,%7}, {%8,%9}, {%0,%1,%2,%3};"
                 : "+f"(c[0]), "+f"(c[1]), "+f"(c[2]), "+f"(c[3])
                 : "r"(a[0]), "r"(a[1]), "r"(a[2]), "r"(a[3]),
                   "r"(b0), "r"(b1));
}
__device__ __forceinline__ void cp16(uint32_t* smem, const uint32_t* g) {
    uint32_t a = (uint32_t)__cvta_generic_to_shared(smem);
    asm volatile("cp.async.cg.shared.global [%0], [%1], 16;" :: "r"(a), "l"(g));
}

// ---------------- operand conversion (once, vectorized) ----------------------
__global__ void convert_kernel(const float* __restrict__ xq,
                               const float* __restrict__ xc,
                               const float* __restrict__ W0,
                               const float* __restrict__ W1,
                               const float* __restrict__ W2) {
    int t = blockIdx.x * blockDim.x + threadIdx.x;   // quad index
    const int NXQ = 2 * NN * XW / 4;                 // 1,048,576 x-quads
    if (t < NXQ) {
        int row = t >> 6;                            // 64 quads per row
        int q   = t & 63;
        const float* src = (row < NN) ? (xq + (size_t)row * FIN0 + q * 8)
                                      : (xc + (size_t)(row - NN) * FIN0 + q * 8);
        float4 v0 = *(const float4*)src;
        float4 v1 = *(const float4*)(src + 4);
        uint4 o;
        o.x = pack_bf16x2(v0.x, v0.y); o.y = pack_bf16x2(v0.z, v0.w);
        o.z = pack_bf16x2(v1.x, v1.y); o.w = pack_bf16x2(v1.z, v1.w);
        *(uint4*)&g_xb[(size_t)row * XW + q * 4] = o;
        return;
    }
    int u = t - NXQ;
    const float* W; uint32_t* Wo; int nq;
    if (u < 16384)       { W = W0; Wo = g_wb0; nq = u; }
    else if (u < 24576)  { W = W1; Wo = g_wb1; nq = u - 16384; }
    else if (u < 32768)  { W = W2; Wo = g_wb2; nq = u - 24576; }
    else return;
    int kp = nq >> 6;                                // 64 quads per kp row
    int n4 = (nq & 63) * 4;
    float4 a = *(const float4*)&W[(size_t)(2 * kp) * FD + n4];
    float4 b = *(const float4*)&W[(size_t)(2 * kp + 1) * FD + n4];
    uint4 o;
    o.x = pack_bf16x2(a.x, b.x); o.y = pack_bf16x2(a.y, b.y);
    o.z = pack_bf16x2(a.z, b.z); o.w = pack_bf16x2(a.w, b.w);
    *(uint4*)&Wo[(size_t)kp * FD + n4] = o;
}

// ---------------- dense adjacency counts -------------------------------------
__global__ void cnt_kernel(const int* __restrict__ eq,
                           const int* __restrict__ ec) {
    int t = blockIdx.x * blockDim.x + threadIdx.x;   // 2*NE
    int g = (t < NE) ? 0 : 1;
    int e = t - g * NE;
    const int* ei = g ? ec : eq;
    int src = ei[e];
    int dst = ei[NE + e];
    int graph = g * NB + (dst >> 5);
    atomicAdd(&g_adjcnt[graph * (SS * SS) + (dst & 31) * SS + (src & 31)], 1);
}

__global__ void adj_prep_kernel() {       // grid NG, block 32
    int g = blockIdx.x;
    int d = threadIdx.x;
    __shared__ float sdinv[SS];
    const int* cnt = g_adjcnt + g * (SS * SS) + d * SS;
    int deg = 1;                           // self loop
#pragma unroll
    for (int s = 0; s < SS; s++) deg += cnt[s];
    float di = rsqrtf((float)deg);
    sdinv[d] = di;
    __syncwarp();
    uint32_t* outp = g_adjP + g * (SS * 16) + d * 16;
#pragma unroll
    for (int p = 0; p < 16; p++) {
        float a0 = cnt[2 * p]     * di * sdinv[2 * p];
        float a1 = cnt[2 * p + 1] * di * sdinv[2 * p + 1];
        if (d == 2 * p)     a0 += di * di;
        if (d == 2 * p + 1) a1 += di * di;
        outp[p] = pack_bf16x2(a0, a1);
    }
}

// ---------------- fused GCN layer: 3-stage cp.async, 1 bar per stage ---------
// Fo = Ahat_blockdiag @ (A @ W) + bias ;  Fr = relu(Fo)  (all bf16 operands)
__global__ void __launch_bounds__(256, 2)
layer_kernel(const uint32_t* __restrict__ Ab, int rowW,
             const uint32_t* __restrict__ Wb,
             const float* __restrict__ bias,
             int K, uint32_t* __restrict__ Fo, uint32_t* __restrict__ Fr) {
    extern __shared__ __align__(16) uint32_t dsm[];

    const int tid   = threadIdx.x;
    const int lane  = tid & 31;
    const int warp  = tid >> 5;
    const int warpM = warp >> 1;     // graph within tile
    const int warpN = warp & 1;      // 64-col half
    const int row0  = blockIdx.y * 128;
    const int col0  = blockIdx.x * 128;

    const int la = lane & 3;
    const int lb = lane >> 2;

    float acc[2][8][4];
#pragma unroll
    for (int mt = 0; mt < 2; mt++)
#pragma unroll
        for (int nt = 0; nt < 8; nt++)
#pragma unroll
            for (int e = 0; e < 4; e++) acc[mt][nt][e] = 0.f;

    // loader mapping: A 128x16 words (512 uint4), B 16x128 words (512 uint4)
    const int aR  = tid >> 2,         aW  = (tid & 3) * 4;
    const int aR2 = (tid + 256) >> 2, aW2 = ((tid + 256) & 3) * 4;
    const int bK  = tid >> 5,         bW  = (tid & 31) * 4;
    const int bK2 = (tid + 256) >> 5, bW2 = ((tid + 256) & 31) * 4;

    const int nIt = K >> 5;
#define LOAD_STAGE(it, buf)                                                     \
    do {                                                                        \
        int kw = (it) * 16;                                                     \
        uint32_t* Asb = dsm + (buf) * AS_STAGE;                                 \
        uint32_t* Bsb = dsm + BS_BASE + (buf) * BS_STAGE;                       \
        cp16(Asb + aR * AS_STRIDE + aW,                                         \
             Ab + (size_t)(row0 + aR) * rowW + kw + aW);                        \
        cp16(Asb + aR2 * AS_STRIDE + aW2,                                       \
             Ab + (size_t)(row0 + aR2) * rowW + kw + aW2);                      \
        cp16(Bsb + bK * BS_STRIDE + bW,                                         \
             Wb + (size_t)(kw + bK) * FD + col0 + bW);                          \
        cp16(Bsb + bK2 * BS_STRIDE + bW2,                                       \
             Wb + (size_t)(kw + bK2) * FD + col0 + bW2);                        \
        asm volatile("cp.async.commit_group;");                                 \
    } while (0)

    LOAD_STAGE(0, 0);
    LOAD_STAGE(1, 1);
    for (int it = 0; it < nIt; it++) {
        asm volatile("cp.async.wait_group 1;");
        __syncthreads();
        // safe: buffer (it+2)%3 was last READ at stage it-1, and this barrier
        // guarantees every warp finished stage it-1's compute.
        if (it + 2 < nIt) LOAD_STAGE(it + 2, (it + 2) % 3);
        const uint32_t* Asb = dsm + (it % 3) * AS_STAGE;
        const uint32_t* Bsb = dsm + BS_BASE + (it % 3) * BS_STAGE;
#pragma unroll
        for (int kk2 = 0; kk2 < 16; kk2 += 8) {
            uint32_t a[2][4];
#pragma unroll
            for (int mt = 0; mt < 2; mt++) {
                int r = warpM * 32 + mt * 16 + lb;
                a[mt][0] = Asb[r * AS_STRIDE + kk2 + la];
                a[mt][1] = Asb[(r + 8) * AS_STRIDE + kk2 + la];
                a[mt][2] = Asb[r * AS_STRIDE + kk2 + la + 4];
                a[mt][3] = Asb[(r + 8) * AS_STRIDE + kk2 + la + 4];
            }
#pragma unroll
            for (int nt = 0; nt < 8; nt++) {
                int c = warpN * 64 + nt * 8 + lb;
                uint32_t b0 = Bsb[(kk2 + la) * BS_STRIDE + c];
                uint32_t b1 = Bsb[(kk2 + 4 + la) * BS_STRIDE + c];
                mma16(acc[0][nt], a[0], b0, b1);
                mma16(acc[1][nt], a[1], b0, b1);
            }
        }
    }
#undef LOAD_STAGE
    __syncthreads();    // all compute done before Ts overlays the buffers

    // ---- stage T to smem (bf16, transposed: Ts[col][node], stride 136) ----
    __nv_bfloat16* Ts = (__nv_bfloat16*)dsm;
#pragma unroll
    for (int mt = 0; mt < 2; mt++)
#pragma unroll
        for (int nt = 0; nt < 8; nt++) {
            int r = warpM * 32 + mt * 16 + lb;
            int c = warpN * 64 + nt * 8 + la * 2;
            Ts[c * 136 + r]           = __float2bfloat16(acc[mt][nt][0]);
            Ts[(c + 1) * 136 + r]     = __float2bfloat16(acc[mt][nt][1]);
            Ts[c * 136 + r + 8]       = __float2bfloat16(acc[mt][nt][2]);
            Ts[(c + 1) * 136 + r + 8] = __float2bfloat16(acc[mt][nt][3]);
        }
    __syncthreads();

    // ---- epilogue: D = Ahat(graph) @ T + bias ----
    const int graph = (row0 >> 5) + warpM;
    const uint32_t* AhP = g_adjP + graph * (SS * 16);
    uint32_t af[2][2][4];
#pragma unroll
    for (int mt = 0; mt < 2; mt++)
#pragma unroll
        for (int kk = 0; kk < 2; kk++) {
            af[mt][kk][0] = AhP[(mt * 16 + lb) * 16 + kk * 8 + la];
            af[mt][kk][1] = AhP[(mt * 16 + lb + 8) * 16 + kk * 8 + la];
            af[mt][kk][2] = AhP[(mt * 16 + lb) * 16 + kk * 8 + la + 4];
            af[mt][kk][3] = AhP[(mt * 16 + lb + 8) * 16 + kk * 8 + la + 4];
        }

#pragma unroll
    for (int mt = 0; mt < 2; mt++)
#pragma unroll
        for (int nt = 0; nt < 8; nt++) {
            int c = col0 + warpN * 64 + nt * 8 + la * 2;
            float bx = bias[c], by = bias[c + 1];
            acc[mt][nt][0] = bx; acc[mt][nt][1] = by;
            acc[mt][nt][2] = bx; acc[mt][nt][3] = by;
        }

#pragma unroll
    for (int kk = 0; kk < 2; kk++) {
#pragma unroll
        for (int nt = 0; nt < 8; nt++) {
            int nloc  = warpN * 64 + nt * 8 + lb;
            int nodeb = warpM * 32 + kk * 16 + 2 * la;
            uint32_t b0 = *(const uint32_t*)&Ts[nloc * 136 + nodeb];
            uint32_t b1 = *(const uint32_t*)&Ts[nloc * 136 + nodeb + 8];
            mma16(acc[0][nt], af[0][kk], b0, b1);
            mma16(acc[1][nt], af[1][kk], b0, b1);
        }
    }

    // ---- store features: pre-ReLU (Fo) and post-ReLU (Fr) bf16 pairs ----
#pragma unroll
    for (int mt = 0; mt < 2; mt++)
#pragma unroll
        for (int nt = 0; nt < 8; nt++) {
            int r = row0 + warpM * 32 + mt * 16 + lb;
            int p = (col0 >> 1) + warpN * 32 + nt * 4 + la;
            Fo[(size_t)r * FP + p] =
                pack_bf16x2(acc[mt][nt][0], acc[mt][nt][1]);
            Fo[(size_t)(r + 8) * FP + p] =
                pack_bf16x2(acc[mt][nt][2], acc[mt][nt][3]);
        }
    if (Fr) {
#pragma unroll
        for (int mt = 0; mt < 2; mt++)
#pragma unroll
            for (int nt = 0; nt < 8; nt++) {
                int r = row0 + warpM * 32 + mt * 16 + lb;
                int p = (col0 >> 1) + warpN * 32 + nt * 4 + la;
                Fr[(size_t)r * FP + p] =
                    pack_bf16x2(fmaxf(acc[mt][nt][0], 0.f),
                                fmaxf(acc[mt][nt][1], 0.f));
                Fr[(size_t)(r + 8) * FP + p] =
                    pack_bf16x2(fmaxf(acc[mt][nt][2], 0.f),
                                fmaxf(acc[mt][nt][3], 0.f));
            }
    }
}

// ---------------- fused cost-build + LAP, one block per (b,l) ----------------
// c_ij = min(-q_i.c_j, -(q_i.del) - (c_j.ins))  (Riesen-Bunke reduction)
__device__ __forceinline__ unsigned fkey(float f) {
    unsigned b = __float_as_uint(f);
    return (b & 0x80000000u) ? ~b : (b | 0x80000000u);
}

__global__ void __launch_bounds__(128)
costlap_kernel(const float* __restrict__ del_p,
               const float* __restrict__ ins_p) {
    const int P = blockIdx.x;            // b*LLY + l
    const int b = P / LLY, l = P % LLY;
    __shared__ union {
        struct { uint32_t Qs[32][132]; uint32_t Cs[32][132]; } s;
        float cost[SS * SS];
    } um;
    __shared__ float sDel[32], sIns[32];
    __shared__ float su[SS];
    __shared__ int row4col[SS], col4row[SS], spath[SS];

    const int tid  = threadIdx.x;
    const int lane = tid & 31;
    const int warp = tid >> 5;

    const uint32_t* Fq = g_featb + ((size_t)l * 2 * NN + b * SS) * FP;
    const uint32_t* Fc = g_featb + ((size_t)l * 2 * NN + NN + b * SS) * FP;

#pragma unroll
    for (int it = 0; it < 8; it++) {
        int idx = it * 128 + tid;
        int row = idx >> 5;
        int w4  = (idx & 31) * 4;
        *(uint4*)&um.s.Qs[row][w4] = *(const uint4*)&Fq[row * FP + w4];
        *(uint4*)&um.s.Cs[row][w4] = *(const uint4*)&Fc[row * FP + w4];
    }
    __syncthreads();

    // D = Q @ C^T (16x16 tile per warp)
    const int warpM = warp >> 1, warpN = warp & 1;
    const int la = lane & 3, lb = lane >> 2;
    float acc[2][4];
#pragma unroll
    for (int t = 0; t < 2; t++)
#pragma unroll
        for (int e = 0; e < 4; e++) acc[t][e] = 0.f;

#pragma unroll
    for (int kk = 0; kk < 128; kk += 8) {
        uint32_t a[4];
        int r = warpM * 16 + lb;
        a[0] = um.s.Qs[r][kk + la];
        a[1] = um.s.Qs[r + 8][kk + la];
        a[2] = um.s.Qs[r][kk + la + 4];
        a[3] = um.s.Qs[r + 8][kk + la + 4];
#pragma unroll
        for (int t = 0; t < 2; t++) {
            int c = warpN * 16 + t * 8 + lb;
            uint32_t b0 = um.s.Cs[c][kk + la];
            uint32_t b1 = um.s.Cs[c][kk + la + 4];
            mma16(acc[t], a, b0, b1);
        }
    }

    if (warp == 0) {
        float s = 0.f;
        const float* dp = del_p + l * FD;
#pragma unroll 16
        for (int p = 0; p < FP; p++) {
            __nv_bfloat162 h = *(const __nv_bfloat162*)&um.s.Qs[lane][p];
            float2 f = __bfloat1622float2(h);
            s += f.x * dp[2 * p] + f.y * dp[2 * p + 1];
        }
        sDel[lane] = s;
    } else if (warp == 1) {
        float s = 0.f;
        const float* ip = ins_p + l * FD;
#pragma unroll 16
        for (int p = 0; p < FP; p++) {
            __nv_bfloat162 h = *(const __nv_bfloat162*)&um.s.Cs[lane][p];
            float2 f = __bfloat1622float2(h);
            s += f.x * ip[2 * p] + f.y * ip[2 * p + 1];
        }
        sIns[lane] = s;
    }
    __syncthreads();                       // Qs/Cs reads done; cost may overwrite

#pragma unroll
    for (int t = 0; t < 2; t++) {
        int row = warpM * 16 + lb;
        int col = warpN * 16 + t * 8 + 2 * la;
        um.cost[row * SS + col] =
            fminf(-acc[t][0], -(sDel[row] + sIns[col]));
        um.cost[row * SS + col + 1] =
            fminf(-acc[t][1], -(sDel[row] + sIns[col + 1]));
        um.cost[(row + 8) * SS + col] =
            fminf(-acc[t][2], -(sDel[row + 8] + sIns[col]));
        um.cost[(row + 8) * SS + col + 1] =
            fminf(-acc[t][3], -(sDel[row + 8] + sIns[col + 1]));
    }
    __syncthreads();

    if (warp != 0) return;                 // warp 0 runs the LAP in-place

    su[lane] = 0.f;
    row4col[lane] = -1;
    col4row[lane] = -1;
    float v = 0.f;
    __syncwarp();

    const float FINF = __int_as_float(0x7f800000);
    for (int cur = 0; cur < SS; cur++) {
        float sh = FINF;
        bool sc = false;
        int i = cur;
        float minv = 0.f;
        int sink = -1;
        while (sink < 0) {
            float base = minv - su[i];
            if (!sc) {
                float r = base + um.cost[i * SS + lane] - v;
                if (r < sh) { sh = r; spath[lane] = i; }
            }
            unsigned key = sc ? 0xFFFFFFFFu : fkey(sh);
            unsigned mk = __reduce_min_sync(0xffffffffu, key);
            unsigned ball = __ballot_sync(0xffffffffu, key == mk);
            int mj = __ffs(ball) - 1;
            minv = __shfl_sync(0xffffffffu, sh, mj);
            if (lane == mj) sc = true;
            int r4 = row4col[mj];
            if (r4 < 0) sink = mj; else i = r4;
        }
        if (lane == 0) su[cur] += minv;
        if (sc) {
            float d = minv - sh;
            v -= d;
            if (lane != sink) su[row4col[lane]] += d;
        }
        __syncwarp();
        if (lane == 0) {
            int j = sink;
            while (true) {
                int i2 = spath[j];
                row4col[j] = i2;
                int jn = col4row[i2];
                col4row[i2] = j;
                j = jn;
                if (i2 == cur) break;
            }
        }
        __syncwarp();
    }
    float tot = um.cost[row4col[lane] * SS + lane];
#pragma unroll
    for (int o = 16; o; o >>= 1) tot += __shfl_xor_sync(0xffffffffu, tot, o);
    if (lane == 0) g_mcost[P] = tot;
}

// ---------------- epilogue ---------------------------------------------------
__global__ void final_kernel(const float* __restrict__ ot_w,
                             const float* __restrict__ ot_b,
                             float* __restrict__ out) {
    int b = threadIdx.x;   // 256
    float s = ot_b[0];
#pragma unroll
    for (int l = 0; l < LLY; l++)
        s += (g_mcost[b * LLY + l] * (1.0f / 32.0f)) * ot_w[l];
    out[b] = 1.f / (1.f + expf(-s));
}

// ---------------- launch -----------------------------------------------------
extern "C" void kernel_launch(void* const* d_in, const int* in_sizes, int n_in,
                              void* d_out, int out_size) {
    const float* x_q   = (const float*)d_in[0];
    const float* x_c   = (const float*)d_in[1];
    const float* W0    = (const float*)d_in[2];
    const float* b0    = (const float*)d_in[3];
    const float* W1    = (const float*)d_in[4];
    const float* b1    = (const float*)d_in[5];
    const float* W2    = (const float*)d_in[6];
    const float* b2    = (const float*)d_in[7];
    const float* del_p = (const float*)d_in[8];
    const float* ins_p = (const float*)d_in[9];
    const float* ot_w  = (const float*)d_in[10];
    const float* ot_b  = (const float*)d_in[11];
    const int*   eq    = (const int*)d_in[12];
    const int*   ec    = (const int*)d_in[13];
    float* out = (float*)d_out;

    static bool attrSet = false;
    if (!attrSet) {
        cudaFuncSetAttribute(layer_kernel,
                             cudaFuncAttributeMaxDynamicSharedMemorySize,
                             DSM_BYTES);
        attrSet = true;
    }

    void *cntPtr, *xbPtr, *wb0Ptr, *wb1Ptr, *wb2Ptr, *fbPtr, *frPtr;
    cudaGetSymbolAddress(&cntPtr, g_adjcnt);
    cudaGetSymbolAddress(&xbPtr, g_xb);
    cudaGetSymbolAddress(&wb0Ptr, g_wb0);
    cudaGetSymbolAddress(&wb1Ptr, g_wb1);
    cudaGetSymbolAddress(&wb2Ptr, g_wb2);
    cudaGetSymbolAddress(&fbPtr, g_featb);
    cudaGetSymbolAddress(&frPtr, g_featr);
    uint32_t* xb  = (uint32_t*)xbPtr;
    uint32_t* wb0 = (uint32_t*)wb0Ptr;
    uint32_t* wb1 = (uint32_t*)wb1Ptr;
    uint32_t* wb2 = (uint32_t*)wb2Ptr;
    uint32_t* fb  = (uint32_t*)fbPtr;
    uint32_t* fr  = (uint32_t*)frPtr;
    const size_t FSTR = (size_t)2 * NN * FP;

    cudaMemsetAsync(cntPtr, 0, NG * SS * SS * sizeof(int));
    convert_kernel<<<4224, 256>>>(x_q, x_c, W0, W1, W2);
    cnt_kernel<<<512, 256>>>(eq, ec);
    adj_prep_kernel<<<NG, 32>>>();

    layer_kernel<<<dim3(2, 128), 256, DSM_BYTES>>>(xb, XW, wb0, b0, FIN0,
                                                   fb, fr);
    layer_kernel<<<dim3(2, 128), 256, DSM_BYTES>>>(fr, FP, wb1, b1, FD,
                                                   fb + FSTR, fr + FSTR);
    layer_kernel<<<dim3(2, 128), 256, DSM_BYTES>>>(fr + FSTR, FP, wb2, b2, FD,
                                                   fb + 2 * FSTR, nullptr);

    costlap_kernel<<<NB * LLY, 128>>>(del_p, ins_p);
    final_kernel<<<1, 256>>>(ot_w, ot_b, out);
}

// round 12
// speedup vs baseline: 1.0353x; 1.0353x over previous
#include <cuda_runtime.h>
#include <math.h>
#include <stdint.h>
#include <cuda_bf16.h>

#define NN   8192      // nodes per graph side (B*S)
#define FD   256       // hidden dim
#define FIN0 512       // input dim
#define NE   65536     // directed edges per graph (already symmetric)
#define NB   256       // batch
#define SS   32        // nodes per graph
#define LLY  3         // layers
#define NG   (2 * NB)  // total graphs (q side then c side)
#define FP   (FD / 2)  // bf16 pairs per feature row (128)
#define XW   (FIN0 / 2)// bf16 pairs per input row (256)

// ---------------- scratch (static device globals; no allocation) -------------
__device__ int      g_adjcnt[NG * SS * SS];
__device__ uint32_t g_adjP[NG * SS * 16];            // normalized adjacency bf16x2
__device__ uint32_t g_xb[2 * NN * XW];               // input x as bf16 pairs
__device__ uint32_t g_wb0[(FIN0 / 2) * FD];          // W0 packed (k,k+1) pairs
__device__ uint32_t g_wb1[(FD / 2) * FD];
__device__ uint32_t g_wb2[(FD / 2) * FD];
__device__ uint32_t g_featb[LLY * 2 * NN * FP];      // pre-ReLU features (bf16)
__device__ uint32_t g_featr[2 * 2 * NN * FP];        // post-ReLU features (bf16)
__device__ float    g_mcost[NB * LLY];

// ---------------- helpers ----------------------------------------------------
__device__ __forceinline__ uint32_t pack_bf16x2(float lo, float hi) {
    uint32_t r;
    asm("cvt.rn.bf16x2.f32 %0, %1, %2;" : "=r"(r) : "f"(hi), "f"(lo));
    return r;
}
__device__ __forceinline__ void mma16(float* c, const uint32_t* a,
                                      uint32_t b0, uint32_t b1) {
    asm volatile("mma.sync.aligned.m16n8k16.row.col.f32.bf16.bf16.f32 "
                 "{%0,%1,%2,%3}, {%4,%5,%6,%7}, {%8,%9}, {%0,%1,%2,%3};"
                 : "+f"(c[0]), "+f"(c[1]), "+f"(c[2]), "+f"(c[3])
                 : "r"(a[0]), "r"(a[1]), "r"(a[2]), "r"(a[3]),
                   "r"(b0), "r"(b1));
}

// ---------------- operand conversion + adjcnt zeroing (once) -----------------
__global__ void convert_kernel(const float* __restrict__ xq,
                               const float* __restrict__ xc,
                               const float* __restrict__ W0,
                               const float* __restrict__ W1,
                               const float* __restrict__ W2) {
    int t = blockIdx.x * blockDim.x + threadIdx.x;   // quad index
    const int NXQ = 2 * NN * XW / 4;                 // 1,048,576 x-quads
    if (t < NXQ) {
        int row = t >> 6;                            // 64 quads per row
        int q   = t & 63;
        const float* src = (row < NN) ? (xq + (size_t)row * FIN0 + q * 8)
                                      : (xc + (size_t)(row - NN) * FIN0 + q * 8);
        float4 v0 = *(const float4*)src;
        float4 v1 = *(const float4*)(src + 4);
        uint4 o;
        o.x = pack_bf16x2(v0.x, v0.y); o.y = pack_bf16x2(v0.z, v0.w);
        o.z = pack_bf16x2(v1.x, v1.y); o.w = pack_bf16x2(v1.z, v1.w);
        *(uint4*)&g_xb[(size_t)row * XW + q * 4] = o;
        return;
    }
    int u = t - NXQ;
    if (u < 32768) {                                 // weight packing
        const float* W; uint32_t* Wo; int nq;
        if (u < 16384)      { W = W0; Wo = g_wb0; nq = u; }
        else if (u < 24576) { W = W1; Wo = g_wb1; nq = u - 16384; }
        else                { W = W2; Wo = g_wb2; nq = u - 24576; }
        int kp = nq >> 6;                            // 64 quads per kp row
        int n4 = (nq & 63) * 4;
        float4 a = *(const float4*)&W[(size_t)(2 * kp) * FD + n4];
        float4 b = *(const float4*)&W[(size_t)(2 * kp + 1) * FD + n4];
        uint4 o;
        o.x = pack_bf16x2(a.x, b.x); o.y = pack_bf16x2(a.y, b.y);
        o.z = pack_bf16x2(a.z, b.z); o.w = pack_bf16x2(a.w, b.w);
        *(uint4*)&Wo[(size_t)kp * FD + n4] = o;
        return;
    }
    int z = u - 32768;                               // zero g_adjcnt (131072 uint4)
    if (z < NG * SS * SS / 4)
        *(uint4*)&g_adjcnt[z * 4] = make_uint4(0, 0, 0, 0);
}

// ---------------- dense adjacency counts -------------------------------------
__global__ void cnt_kernel(const int* __restrict__ eq,
                           const int* __restrict__ ec) {
    int t = blockIdx.x * blockDim.x + threadIdx.x;   // 2*NE
    int g = (t < NE) ? 0 : 1;
    int e = t - g * NE;
    const int* ei = g ? ec : eq;
    int src = ei[e];
    int dst = ei[NE + e];
    int graph = g * NB + (dst >> 5);
    atomicAdd(&g_adjcnt[graph * (SS * SS) + (dst & 31) * SS + (src & 31)], 1);
}

__global__ void adj_prep_kernel() {       // grid NG, block 32
    int g = blockIdx.x;
    int d = threadIdx.x;
    __shared__ float sdinv[SS];
    const int* cnt = g_adjcnt + g * (SS * SS) + d * SS;
    int deg = 1;                           // self loop
#pragma unroll
    for (int s = 0; s < SS; s++) deg += cnt[s];
    float di = rsqrtf((float)deg);
    sdinv[d] = di;
    __syncwarp();
    uint32_t* outp = g_adjP + g * (SS * 16) + d * 16;
#pragma unroll
    for (int p = 0; p < 16; p++) {
        float a0 = cnt[2 * p]     * di * sdinv[2 * p];
        float a1 = cnt[2 * p + 1] * di * sdinv[2 * p + 1];
        if (d == 2 * p)     a0 += di * di;
        if (d == 2 * p + 1) a1 += di * di;
        outp[p] = pack_bf16x2(a0, a1);
    }
}

// ---------------- fused GCN layer: LDG register double-buffer ----------------
// Fo = Ahat_blockdiag @ (A @ W) + bias ;  Fr = relu(Fo)  (all bf16 operands)
struct SmemLayer {
    union {
        struct {
            uint32_t As[128][20];          // [m][k-pair]
            uint32_t Bs[16][136];          // [k-pair][n]
        } mm;
        __nv_bfloat16 Ts[128][136];        // [col][node]
    } u;
};

__global__ void __launch_bounds__(256, 2)
layer_kernel(const uint32_t* __restrict__ Ab, int rowW,
             const uint32_t* __restrict__ Wb,
             const float* __restrict__ bias,
             int K, uint32_t* __restrict__ Fo, uint32_t* __restrict__ Fr) {
    __shared__ SmemLayer sm;

    const int tid   = threadIdx.x;
    const int lane  = tid & 31;
    const int warp  = tid >> 5;
    const int warpM = warp >> 1;     // graph within tile
    const int warpN = warp & 1;      // 64-col half
    const int row0  = blockIdx.y * 128;
    const int col0  = blockIdx.x * 128;

    const int la = lane & 3;
    const int lb = lane >> 2;

    float acc[2][8][4];
#pragma unroll
    for (int mt = 0; mt < 2; mt++)
#pragma unroll
        for (int nt = 0; nt < 8; nt++)
#pragma unroll
            for (int e = 0; e < 4; e++) acc[mt][nt][e] = 0.f;

    // loader mapping: A 128x16 words (512 uint4), B 16x128 words (512 uint4)
    const int aR  = tid >> 2,         aW  = (tid & 3) * 4;
    const int aR2 = (tid + 256) >> 2, aW2 = ((tid + 256) & 3) * 4;
    const int bK  = tid >> 5,         bW  = (tid & 31) * 4;
    const int bK2 = (tid + 256) >> 5, bW2 = ((tid + 256) & 31) * 4;

    const uint32_t* aSrc0 = Ab + (size_t)(row0 + aR)  * rowW + aW;
    const uint32_t* aSrc1 = Ab + (size_t)(row0 + aR2) * rowW + aW2;
    const uint32_t* bSrc0 = Wb + (size_t)bK  * FD + col0 + bW;
    const uint32_t* bSrc1 = Wb + (size_t)bK2 * FD + col0 + bW2;

    const int nIt = K >> 5;
    uint4 ra0, ra1, rb0, rb1;

    // prefetch stage 0
    ra0 = *(const uint4*)(aSrc0);
    ra1 = *(const uint4*)(aSrc1);
    rb0 = *(const uint4*)(bSrc0);
    rb1 = *(const uint4*)(bSrc1);

    for (int it = 0; it < nIt; it++) {
        *(uint4*)&sm.u.mm.As[aR][aW]   = ra0;
        *(uint4*)&sm.u.mm.As[aR2][aW2] = ra1;
        *(uint4*)&sm.u.mm.Bs[bK][bW]   = rb0;
        *(uint4*)&sm.u.mm.Bs[bK2][bW2] = rb1;
        __syncthreads();

        if (it + 1 < nIt) {             // prefetch next stage; overlaps compute
            int kw = (it + 1) * 16;
            ra0 = *(const uint4*)(aSrc0 + kw);
            ra1 = *(const uint4*)(aSrc1 + kw);
            rb0 = *(const uint4*)(bSrc0 + (size_t)kw * FD);
            rb1 = *(const uint4*)(bSrc1 + (size_t)kw * FD);
        }

#pragma unroll
        for (int kk2 = 0; kk2 < 16; kk2 += 8) {
            uint32_t a[2][4];
#pragma unroll
            for (int mt = 0; mt < 2; mt++) {
                int r = warpM * 32 + mt * 16 + lb;
                a[mt][0] = sm.u.mm.As[r][kk2 + la];
                a[mt][1] = sm.u.mm.As[r + 8][kk2 + la];
                a[mt][2] = sm.u.mm.As[r][kk2 + la + 4];
                a[mt][3] = sm.u.mm.As[r + 8][kk2 + la + 4];
            }
#pragma unroll
            for (int nt = 0; nt < 8; nt++) {
                int c = warpN * 64 + nt * 8 + lb;
                uint32_t b0 = sm.u.mm.Bs[kk2 + la][c];
                uint32_t b1 = sm.u.mm.Bs[kk2 + 4 + la][c];
                mma16(acc[0][nt], a[0], b0, b1);
                mma16(acc[1][nt], a[1], b0, b1);
            }
        }
        __syncthreads();
    }

    // ---- stage T to smem (bf16, transposed: Ts[col][node]) ----
#pragma unroll
    for (int mt = 0; mt < 2; mt++)
#pragma unroll
        for (int nt = 0; nt < 8; nt++) {
            int r = warpM * 32 + mt * 16 + lb;
            int c = warpN * 64 + nt * 8 + la * 2;
            sm.u.Ts[c][r]         = __float2bfloat16(acc[mt][nt][0]);
            sm.u.Ts[c + 1][r]     = __float2bfloat16(acc[mt][nt][1]);
            sm.u.Ts[c][r + 8]     = __float2bfloat16(acc[mt][nt][2]);
            sm.u.Ts[c + 1][r + 8] = __float2bfloat16(acc[mt][nt][3]);
        }
    __syncthreads();

    // ---- epilogue: D = Ahat(graph) @ T + bias ----
    const int graph = (row0 >> 5) + warpM;
    const uint32_t* AhP = g_adjP + graph * (SS * 16);
    uint32_t af[2][2][4];
#pragma unroll
    for (int mt = 0; mt < 2; mt++)
#pragma unroll
        for (int kk = 0; kk < 2; kk++) {
            af[mt][kk][0] = AhP[(mt * 16 + lb) * 16 + kk * 8 + la];
            af[mt][kk][1] = AhP[(mt * 16 + lb + 8) * 16 + kk * 8 + la];
            af[mt][kk][2] = AhP[(mt * 16 + lb) * 16 + kk * 8 + la + 4];
            af[mt][kk][3] = AhP[(mt * 16 + lb + 8) * 16 + kk * 8 + la + 4];
        }

#pragma unroll
    for (int mt = 0; mt < 2; mt++)
#pragma unroll
        for (int nt = 0; nt < 8; nt++) {
            int c = col0 + warpN * 64 + nt * 8 + la * 2;
            float bx = bias[c], by = bias[c + 1];
            acc[mt][nt][0] = bx; acc[mt][nt][1] = by;
            acc[mt][nt][2] = bx; acc[mt][nt][3] = by;
        }

#pragma unroll
    for (int kk = 0; kk < 2; kk++) {
#pragma unroll
        for (int nt = 0; nt < 8; nt++) {
            int nloc  = warpN * 64 + nt * 8 + lb;
            int nodeb = warpM * 32 + kk * 16 + 2 * la;
            uint32_t b0 = *(const uint32_t*)&sm.u.Ts[nloc][nodeb];
            uint32_t b1 = *(const uint32_t*)&sm.u.Ts[nloc][nodeb + 8];
            mma16(acc[0][nt], af[0][kk], b0, b1);
            mma16(acc[1][nt], af[1][kk], b0, b1);
        }
    }

    // ---- store features: pre-ReLU (Fo) and post-ReLU (Fr) bf16 pairs ----
#pragma unroll
    for (int mt = 0; mt < 2; mt++)
#pragma unroll
        for (int nt = 0; nt < 8; nt++) {
            int r = row0 + warpM * 32 + mt * 16 + lb;
            int p = (col0 >> 1) + warpN * 32 + nt * 4 + la;
            Fo[(size_t)r * FP + p] =
                pack_bf16x2(acc[mt][nt][0], acc[mt][nt][1]);
            Fo[(size_t)(r + 8) * FP + p] =
                pack_bf16x2(acc[mt][nt][2], acc[mt][nt][3]);
        }
    if (Fr) {
#pragma unroll
        for (int mt = 0; mt < 2; mt++)
#pragma unroll
            for (int nt = 0; nt < 8; nt++) {
                int r = row0 + warpM * 32 + mt * 16 + lb;
                int p = (col0 >> 1) + warpN * 32 + nt * 4 + la;
                Fr[(size_t)r * FP + p] =
                    pack_bf16x2(fmaxf(acc[mt][nt][0], 0.f),
                                fmaxf(acc[mt][nt][1], 0.f));
                Fr[(size_t)(r + 8) * FP + p] =
                    pack_bf16x2(fmaxf(acc[mt][nt][2], 0.f),
                                fmaxf(acc[mt][nt][3], 0.f));
            }
    }
}

// ---------------- fused cost-build + LAP, one block per (b,l) ----------------
// c_ij = min(-q_i.c_j, -(q_i.del) - (c_j.ins))  (Riesen-Bunke reduction)
__device__ __forceinline__ unsigned fkey(float f) {
    unsigned b = __float_as_uint(f);
    return (b & 0x80000000u) ? ~b : (b | 0x80000000u);
}

__global__ void __launch_bounds__(128)
costlap_kernel(const float* __restrict__ del_p,
               const float* __restrict__ ins_p) {
    const int P = blockIdx.x;            // b*LLY + l
    const int b = P / LLY, l = P % LLY;
    __shared__ union {
        struct { uint32_t Qs[32][132]; uint32_t Cs[32][132]; } s;
        float cost[SS * SS];
    } um;
    __shared__ float sDel[32], sIns[32];
    __shared__ float su[SS];
    __shared__ int row4col[SS], col4row[SS], spath[SS];

    const int tid  = threadIdx.x;
    const int lane = tid & 31;
    const int warp = tid >> 5;

    const uint32_t* Fq = g_featb + ((size_t)l * 2 * NN + b * SS) * FP;
    const uint32_t* Fc = g_featb + ((size_t)l * 2 * NN + NN + b * SS) * FP;

#pragma unroll
    for (int it = 0; it < 8; it++) {
        int idx = it * 128 + tid;
        int row = idx >> 5;
        int w4  = (idx & 31) * 4;
        *(uint4*)&um.s.Qs[row][w4] = *(const uint4*)&Fq[row * FP + w4];
        *(uint4*)&um.s.Cs[row][w4] = *(const uint4*)&Fc[row * FP + w4];
    }
    __syncthreads();

    // D = Q @ C^T (16x16 tile per warp)
    const int warpM = warp >> 1, warpN = warp & 1;
    const int la = lane & 3, lb = lane >> 2;
    float acc[2][4];
#pragma unroll
    for (int t = 0; t < 2; t++)
#pragma unroll
        for (int e = 0; e < 4; e++) acc[t][e] = 0.f;

#pragma unroll
    for (int kk = 0; kk < 128; kk += 8) {
        uint32_t a[4];
        int r = warpM * 16 + lb;
        a[0] = um.s.Qs[r][kk + la];
        a[1] = um.s.Qs[r + 8][kk + la];
        a[2] = um.s.Qs[r][kk + la + 4];
        a[3] = um.s.Qs[r + 8][kk + la + 4];
#pragma unroll
        for (int t = 0; t < 2; t++) {
            int c = warpN * 16 + t * 8 + lb;
            uint32_t b0 = um.s.Cs[c][kk + la];
            uint32_t b1 = um.s.Cs[c][kk + la + 4];
            mma16(acc[t], a, b0, b1);
        }
    }

    if (warp == 0) {
        float s = 0.f;
        const float* dp = del_p + l * FD;
#pragma unroll 16
        for (int p = 0; p < FP; p++) {
            __nv_bfloat162 h = *(const __nv_bfloat162*)&um.s.Qs[lane][p];
            float2 f = __bfloat1622float2(h);
            s += f.x * dp[2 * p] + f.y * dp[2 * p + 1];
        }
        sDel[lane] = s;
    } else if (warp == 1) {
        float s = 0.f;
        const float* ip = ins_p + l * FD;
#pragma unroll 16
        for (int p = 0; p < FP; p++) {
            __nv_bfloat162 h = *(const __nv_bfloat162*)&um.s.Cs[lane][p];
            float2 f = __bfloat1622float2(h);
            s += f.x * ip[2 * p] + f.y * ip[2 * p + 1];
        }
        sIns[lane] = s;
    }
    __syncthreads();                       // Qs/Cs reads done; cost may overwrite

#pragma unroll
    for (int t = 0; t < 2; t++) {
        int row = warpM * 16 + lb;
        int col = warpN * 16 + t * 8 + 2 * la;
        um.cost[row * SS + col] =
            fminf(-acc[t][0], -(sDel[row] + sIns[col]));
        um.cost[row * SS + col + 1] =
            fminf(-acc[t][1], -(sDel[row] + sIns[col + 1]));
        um.cost[(row + 8) * SS + col] =
            fminf(-acc[t][2], -(sDel[row + 8] + sIns[col]));
        um.cost[(row + 8) * SS + col + 1] =
            fminf(-acc[t][3], -(sDel[row + 8] + sIns[col + 1]));
    }
    __syncthreads();

    if (warp != 0) return;                 // warp 0 runs the LAP in-place

    su[lane] = 0.f;
    row4col[lane] = -1;
    col4row[lane] = -1;
    float v = 0.f;
    __syncwarp();

    const float FINF = __int_as_float(0x7f800000);
    for (int cur = 0; cur < SS; cur++) {
        float sh = FINF;
        bool sc = false;
        int i = cur;
        float minv = 0.f;
        int sink = -1;
        while (sink < 0) {
            float base = minv - su[i];
            if (!sc) {
                float r = base + um.cost[i * SS + lane] - v;
                if (r < sh) { sh = r; spath[lane] = i; }
            }
            unsigned key = sc ? 0xFFFFFFFFu : fkey(sh);
            unsigned mk = __reduce_min_sync(0xffffffffu, key);
            unsigned ball = __ballot_sync(0xffffffffu, key == mk);
            int mj = __ffs(ball) - 1;
            minv = __shfl_sync(0xffffffffu, sh, mj);
            if (lane == mj) sc = true;
            int r4 = row4col[mj];
            if (r4 < 0) sink = mj; else i = r4;
        }
        if (lane == 0) su[cur] += minv;
        if (sc) {
            float d = minv - sh;
            v -= d;
            if (lane != sink) su[row4col[lane]] += d;
        }
        __syncwarp();
        if (lane == 0) {
            int j = sink;
            while (true) {
                int i2 = spath[j];
                row4col[j] = i2;
                int jn = col4row[i2];
                col4row[i2] = j;
                j = jn;
                if (i2 == cur) break;
            }
        }
        __syncwarp();
    }
    float tot = um.cost[row4col[lane] * SS + lane];
#pragma unroll
    for (int o = 16; o; o >>= 1) tot += __shfl_xor_sync(0xffffffffu, tot, o);
    if (lane == 0) g_mcost[P] = tot;
}

// ---------------- epilogue ---------------------------------------------------
__global__ void final_kernel(const float* __restrict__ ot_w,
                             const float* __restrict__ ot_b,
                             float* __restrict__ out) {
    int b = threadIdx.x;   // 256
    float s = ot_b[0];
#pragma unroll
    for (int l = 0; l < LLY; l++)
        s += (g_mcost[b * LLY + l] * (1.0f / 32.0f)) * ot_w[l];
    out[b] = 1.f / (1.f + expf(-s));
}

// ---------------- launch -----------------------------------------------------
extern "C" void kernel_launch(void* const* d_in, const int* in_sizes, int n_in,
                              void* d_out, int out_size) {
    const float* x_q   = (const float*)d_in[0];
    const float* x_c   = (const float*)d_in[1];
    const float* W0    = (const float*)d_in[2];
    const float* b0    = (const float*)d_in[3];
    const float* W1    = (const float*)d_in[4];
    const float* b1    = (const float*)d_in[5];
    const float* W2    = (const float*)d_in[6];
    const float* b2    = (const float*)d_in[7];
    const float* del_p = (const float*)d_in[8];
    const float* ins_p = (const float*)d_in[9];
    const float* ot_w  = (const float*)d_in[10];
    const float* ot_b  = (const float*)d_in[11];
    const int*   eq    = (const int*)d_in[12];
    const int*   ec    = (const int*)d_in[13];
    float* out = (float*)d_out;

    void *xbPtr, *wb0Ptr, *wb1Ptr, *wb2Ptr, *fbPtr, *frPtr;
    cudaGetSymbolAddress(&xbPtr, g_xb);
    cudaGetSymbolAddress(&wb0Ptr, g_wb0);
    cudaGetSymbolAddress(&wb1Ptr, g_wb1);
    cudaGetSymbolAddress(&wb2Ptr, g_wb2);
    cudaGetSymbolAddress(&fbPtr, g_featb);
    cudaGetSymbolAddress(&frPtr, g_featr);
    uint32_t* xb  = (uint32_t*)xbPtr;
    uint32_t* wb0 = (uint32_t*)wb0Ptr;
    uint32_t* wb1 = (uint32_t*)wb1Ptr;
    uint32_t* wb2 = (uint32_t*)wb2Ptr;
    uint32_t* fb  = (uint32_t*)fbPtr;
    uint32_t* fr  = (uint32_t*)frPtr;
    const size_t FSTR = (size_t)2 * NN * FP;

    // convert also zeroes g_adjcnt: 1,048,576 + 32,768 + 131,072 quads
    convert_kernel<<<4736, 256>>>(x_q, x_c, W0, W1, W2);
    cnt_kernel<<<512, 256>>>(eq, ec);
    adj_prep_kernel<<<NG, 32>>>();

    layer_kernel<<<dim3(2, 128), 256>>>(xb, XW, wb0, b0, FIN0, fb, fr);
    layer_kernel<<<dim3(2, 128), 256>>>(fr, FP, wb1, b1, FD,
                                        fb + FSTR, fr + FSTR);
    layer_kernel<<<dim3(2, 128), 256>>>(fr + FSTR, FP, wb2, b2, FD,
                                        fb + 2 * FSTR, nullptr);

    costlap_kernel<<<NB * LLY, 128>>>(del_p, ins_p);
    final_kernel<<<1, 256>>>(ot_w, ot_b, out);
}

// round 13
// speedup vs baseline: 1.0852x; 1.0482x over previous
#include <cuda_runtime.h>
#include <math.h>
#include <stdint.h>
#include <cuda_bf16.h>

#define NN   8192      // nodes per graph side (B*S)
#define FD   256       // hidden dim
#define FIN0 512       // input dim
#define NE   65536     // directed edges per graph (already symmetric)
#define NB   256       // batch
#define SS   32        // nodes per graph
#define LLY  3         // layers
#define NG   (2 * NB)  // total graphs (q side then c side)
#define FP   (FD / 2)  // bf16 pairs per feature row (128)
#define XW   (FIN0 / 2)// bf16 pairs per input row (256)

// ---- mega-kernel dynamic smem layout (uint32 word offsets) ------------------
#define W_BS    0                        // Bs[2][16][264]
#define W_AS    (2 * 16 * 264)           // 8448:  As[2][128][20]
#define W_FCUR  (W_AS + 2 * 128 * 20)    // 13568: Fcur[128][132] (post-ReLU)
#define W_TS    (W_FCUR + 128 * 132)     // 30464: Ts bf16[256][136] / Fpre[128][132]
#define W_COST  (W_TS + 17408)           // 47872: cost[6][32*33] floats
#define W_DOT   (W_COST + 6 * 32 * 33)   // 54208: dot[128] floats
#define W_SU    (W_DOT + 128)            // 54336
#define W_R4C   (W_SU + 192)
#define W_C4R   (W_R4C + 192)
#define W_PATH  (W_C4R + 192)
#define W_MC    (W_PATH + 192)
#define W_TOT   (W_MC + 8)               // 55112 words
#define DSM_BYTES (W_TOT * 4)            // 220448 bytes

// ---------------- scratch (static device globals; no allocation) -------------
__device__ int      g_adjcnt[NG * SS * SS];
__device__ uint32_t g_adjP[NG * SS * 16];            // normalized adjacency bf16x2
__device__ uint32_t g_xb[2 * NN * XW];               // input x as bf16 pairs
__device__ uint32_t g_wb0[(FIN0 / 2) * FD];          // W packed (k,k+1) pairs
__device__ uint32_t g_wb1[(FD / 2) * FD];
__device__ uint32_t g_wb2[(FD / 2) * FD];

// ---------------- helpers ----------------------------------------------------
__device__ __forceinline__ uint32_t pack_bf16x2(float lo, float hi) {
    uint32_t r;
    asm("cvt.rn.bf16x2.f32 %0, %1, %2;" : "=r"(r) : "f"(hi), "f"(lo));
    return r;
}
__device__ __forceinline__ void mma16(float* c, const uint32_t* a,
                                      uint32_t b0, uint32_t b1) {
    asm volatile("mma.sync.aligned.m16n8k16.row.col.f32.bf16.bf16.f32 "
                 "{%0,%1,%2,%3}, {%4,%5,%6,%7}, {%8,%9}, {%0,%1,%2,%3};"
                 : "+f"(c[0]), "+f"(c[1]), "+f"(c[2]), "+f"(c[3])
                 : "r"(a[0]), "r"(a[1]), "r"(a[2]), "r"(a[3]),
                   "r"(b0), "r"(b1));
}
__device__ __forceinline__ unsigned fkey(float f) {
    unsigned b = __float_as_uint(f);
    return (b & 0x80000000u) ? ~b : (b | 0x80000000u);
}

// ---------------- operand conversion + adjcnt zeroing (once) -----------------
__global__ void convert_kernel(const float* __restrict__ xq,
                               const float* __restrict__ xc,
                               const float* __restrict__ W0,
                               const float* __restrict__ W1,
                               const float* __restrict__ W2) {
    int t = blockIdx.x * blockDim.x + threadIdx.x;   // quad index
    const int NXQ = 2 * NN * XW / 4;                 // 1,048,576 x-quads
    if (t < NXQ) {
        int row = t >> 6;
        int q   = t & 63;
        const float* src = (row < NN) ? (xq + (size_t)row * FIN0 + q * 8)
                                      : (xc + (size_t)(row - NN) * FIN0 + q * 8);
        float4 v0 = *(const float4*)src;
        float4 v1 = *(const float4*)(src + 4);
        uint4 o;
        o.x = pack_bf16x2(v0.x, v0.y); o.y = pack_bf16x2(v0.z, v0.w);
        o.z = pack_bf16x2(v1.x, v1.y); o.w = pack_bf16x2(v1.z, v1.w);
        *(uint4*)&g_xb[(size_t)row * XW + q * 4] = o;
        return;
    }
    int u = t - NXQ;
    if (u < 32768) {                                 // weight packing
        const float* W; uint32_t* Wo; int nq;
        if (u < 16384)      { W = W0; Wo = g_wb0; nq = u; }
        else if (u < 24576) { W = W1; Wo = g_wb1; nq = u - 16384; }
        else                { W = W2; Wo = g_wb2; nq = u - 24576; }
        int kp = nq >> 6;
        int n4 = (nq & 63) * 4;
        float4 a = *(const float4*)&W[(size_t)(2 * kp) * FD + n4];
        float4 b = *(const float4*)&W[(size_t)(2 * kp + 1) * FD + n4];
        uint4 o;
        o.x = pack_bf16x2(a.x, b.x); o.y = pack_bf16x2(a.y, b.y);
        o.z = pack_bf16x2(a.z, b.z); o.w = pack_bf16x2(a.w, b.w);
        *(uint4*)&Wo[(size_t)kp * FD + n4] = o;
        return;
    }
    int z = u - 32768;                               // zero g_adjcnt
    if (z < NG * SS * SS / 4)
        *(uint4*)&g_adjcnt[z * 4] = make_uint4(0, 0, 0, 0);
}

// ---------------- dense adjacency counts -------------------------------------
__global__ void cnt_kernel(const int* __restrict__ eq,
                           const int* __restrict__ ec) {
    int t = blockIdx.x * blockDim.x + threadIdx.x;   // 2*NE
    int g = (t < NE) ? 0 : 1;
    int e = t - g * NE;
    const int* ei = g ? ec : eq;
    int src = ei[e];
    int dst = ei[NE + e];
    int graph = g * NB + (dst >> 5);
    atomicAdd(&g_adjcnt[graph * (SS * SS) + (dst & 31) * SS + (src & 31)], 1);
}

__global__ void adj_prep_kernel() {       // grid NG, block 32
    int g = blockIdx.x;
    int d = threadIdx.x;
    __shared__ float sdinv[SS];
    const int* cnt = g_adjcnt + g * (SS * SS) + d * SS;
    int deg = 1;                           // self loop
#pragma unroll
    for (int s = 0; s < SS; s++) deg += cnt[s];
    float di = rsqrtf((float)deg);
    sdinv[d] = di;
    __syncwarp();
    uint32_t* outp = g_adjP + g * (SS * 16) + d * 16;
#pragma unroll
    for (int p = 0; p < 16; p++) {
        float a0 = cnt[2 * p]     * di * sdinv[2 * p];
        float a1 = cnt[2 * p + 1] * di * sdinv[2 * p + 1];
        if (d == 2 * p)     a0 += di * di;
        if (d == 2 * p + 1) a1 += di * di;
        outp[p] = pack_bf16x2(a0, a1);
    }
}

// ---------------- MEGA kernel: 3 GCN layers + cost + LAP + score -------------
// Block bb owns q-graphs {2bb,2bb+1} (local rows 0-63) and c-graphs {2bb,2bb+1}
// (local rows 64-127). Everything after input staging lives in shared memory.
__global__ void __launch_bounds__(512, 1)
mega_kernel(const float* __restrict__ del_p, const float* __restrict__ ins_p,
            const float* __restrict__ bias0, const float* __restrict__ bias1,
            const float* __restrict__ bias2,
            const float* __restrict__ ot_w, const float* __restrict__ ot_b,
            float* __restrict__ out) {
    extern __shared__ __align__(16) uint32_t dsm[];
    const int bb   = blockIdx.x;          // 0..127
    const int tid  = threadIdx.x;
    const int lane = tid & 31;
    const int warp = tid >> 5;
    const int wM = warp >> 2, wN = warp & 3;   // 4x4 warp grid, 32x64 tiles
    const int la = lane & 3, lb = lane >> 2;

    uint32_t* Bs   = dsm + W_BS;
    uint32_t* As   = dsm + W_AS;
    uint32_t* Fcur = dsm + W_FCUR;                       // [128][132] post-ReLU
    __nv_bfloat16* Ts = (__nv_bfloat16*)(dsm + W_TS);    // [256][136]
    uint32_t* Fpre = dsm + W_TS;                         // overlay [128][132]
    float* costS = (float*)(dsm + W_COST);               // [6][32*33]
    float* dotS  = (float*)(dsm + W_DOT);                // [128]

    // loader mappings
    const int bkp0 = tid >> 6,         bw0 = (tid & 63) * 4;
    const int bkp1 = (tid + 512) >> 6, bw1 = ((tid + 512) & 63) * 4;
    const int aR = tid >> 2, aW = (tid & 3) * 4;
    const int grA = (aR < 64) ? (64 * bb + aR) : (NN + 64 * bb + aR - 64);
    const uint32_t* aSrc = g_xb + (size_t)grA * XW + aW;

    for (int l = 0; l < LLY; l++) {
        const uint32_t* Wb  = (l == 0) ? g_wb0 : ((l == 1) ? g_wb1 : g_wb2);
        const float* bias   = (l == 0) ? bias0 : ((l == 1) ? bias1 : bias2);

        float acc[2][8][4];
#pragma unroll
        for (int mt = 0; mt < 2; mt++)
#pragma unroll
            for (int nt = 0; nt < 8; nt++)
#pragma unroll
                for (int e = 0; e < 4; e++) acc[mt][nt][e] = 0.f;

        if (l == 0) {
            // ---- GEMM layer 0: A staged from gmem, 16 k-steps ----
            uint4 ra, r0, r1;
            r0 = *(const uint4*)(Wb + (size_t)bkp0 * FD + bw0);
            r1 = *(const uint4*)(Wb + (size_t)bkp1 * FD + bw1);
            ra = *(const uint4*)(aSrc);
            for (int it = 0; it < 16; it++) {
                int buf = it & 1;
                *(uint4*)&Bs[buf * 4224 + bkp0 * 264 + bw0] = r0;
                *(uint4*)&Bs[buf * 4224 + bkp1 * 264 + bw1] = r1;
                *(uint4*)&As[buf * 2560 + aR * 20 + aW]     = ra;
                __syncthreads();
                if (it + 1 < 16) {
                    int kw = (it + 1) * 16;
                    r0 = *(const uint4*)(Wb + (size_t)(kw + bkp0) * FD + bw0);
                    r1 = *(const uint4*)(Wb + (size_t)(kw + bkp1) * FD + bw1);
                    ra = *(const uint4*)(aSrc + kw);
                }
                const uint32_t* Asb = As + buf * 2560;
                const uint32_t* Bsb = Bs + buf * 4224;
#pragma unroll
                for (int kk2 = 0; kk2 < 16; kk2 += 8) {
                    uint32_t a[2][4];
#pragma unroll
                    for (int mt = 0; mt < 2; mt++) {
                        int r = wM * 32 + mt * 16 + lb;
                        a[mt][0] = Asb[r * 20 + kk2 + la];
                        a[mt][1] = Asb[(r + 8) * 20 + kk2 + la];
                        a[mt][2] = Asb[r * 20 + kk2 + la + 4];
                        a[mt][3] = Asb[(r + 8) * 20 + kk2 + la + 4];
                    }
#pragma unroll
                    for (int nt = 0; nt < 8; nt++) {
                        int c = wN * 64 + nt * 8 + lb;
                        uint32_t b0 = Bsb[(kk2 + la) * 264 + c];
                        uint32_t b1 = Bsb[(kk2 + 4 + la) * 264 + c];
                        mma16(acc[0][nt], a[0], b0, b1);
                        mma16(acc[1][nt], a[1], b0, b1);
                    }
                }
                __syncthreads();
            }
        } else {
            // ---- GEMM layers 1-2: A read directly from Fcur (smem) ----
            uint4 r0, r1;
            r0 = *(const uint4*)(Wb + (size_t)bkp0 * FD + bw0);
            r1 = *(const uint4*)(Wb + (size_t)bkp1 * FD + bw1);
            for (int it = 0; it < 8; it++) {
                int buf = it & 1;
                *(uint4*)&Bs[buf * 4224 + bkp0 * 264 + bw0] = r0;
                *(uint4*)&Bs[buf * 4224 + bkp1 * 264 + bw1] = r1;
                __syncthreads();
                if (it + 1 < 8) {
                    int kw = (it + 1) * 16;
                    r0 = *(const uint4*)(Wb + (size_t)(kw + bkp0) * FD + bw0);
                    r1 = *(const uint4*)(Wb + (size_t)(kw + bkp1) * FD + bw1);
                }
                const uint32_t* Bsb = Bs + buf * 4224;
#pragma unroll
                for (int kk2 = 0; kk2 < 16; kk2 += 8) {
                    int kka = it * 16 + kk2 + la;
                    uint32_t a[2][4];
#pragma unroll
                    for (int mt = 0; mt < 2; mt++) {
                        int r = wM * 32 + mt * 16 + lb;
                        a[mt][0] = Fcur[r * 132 + kka];
                        a[mt][1] = Fcur[(r + 8) * 132 + kka];
                        a[mt][2] = Fcur[r * 132 + kka + 4];
                        a[mt][3] = Fcur[(r + 8) * 132 + kka + 4];
                    }
#pragma unroll
                    for (int nt = 0; nt < 8; nt++) {
                        int c = wN * 64 + nt * 8 + lb;
                        uint32_t b0 = Bsb[(kk2 + la) * 264 + c];
                        uint32_t b1 = Bsb[(kk2 + 4 + la) * 264 + c];
                        mma16(acc[0][nt], a[0], b0, b1);
                        mma16(acc[1][nt], a[1], b0, b1);
                    }
                }
                __syncthreads();
            }
        }

        // ---- stage T transposed to smem (bf16 Ts[col][node]) ----
#pragma unroll
        for (int mt = 0; mt < 2; mt++)
#pragma unroll
            for (int nt = 0; nt < 8; nt++) {
                int r = wM * 32 + mt * 16 + lb;
                int c = wN * 64 + nt * 8 + la * 2;
                Ts[c * 136 + r]           = __float2bfloat16(acc[mt][nt][0]);
                Ts[(c + 1) * 136 + r]     = __float2bfloat16(acc[mt][nt][1]);
                Ts[c * 136 + r + 8]       = __float2bfloat16(acc[mt][nt][2]);
                Ts[(c + 1) * 136 + r + 8] = __float2bfloat16(acc[mt][nt][3]);
            }
        __syncthreads();

        // ---- aggregation: D = Ahat(graph) @ T + bias ----
        const int gidx = (wM < 2) ? (2 * bb + wM) : (NB + 2 * bb + (wM - 2));
        const uint32_t* AhP = g_adjP + gidx * 512;
        uint32_t af[2][2][4];
#pragma unroll
        for (int mt = 0; mt < 2; mt++)
#pragma unroll
            for (int kk = 0; kk < 2; kk++) {
                af[mt][kk][0] = AhP[(mt * 16 + lb) * 16 + kk * 8 + la];
                af[mt][kk][1] = AhP[(mt * 16 + lb + 8) * 16 + kk * 8 + la];
                af[mt][kk][2] = AhP[(mt * 16 + lb) * 16 + kk * 8 + la + 4];
                af[mt][kk][3] = AhP[(mt * 16 + lb + 8) * 16 + kk * 8 + la + 4];
            }
#pragma unroll
        for (int mt = 0; mt < 2; mt++)
#pragma unroll
            for (int nt = 0; nt < 8; nt++) {
                int c = wN * 64 + nt * 8 + la * 2;
                float bx = bias[c], by = bias[c + 1];
                acc[mt][nt][0] = bx; acc[mt][nt][1] = by;
                acc[mt][nt][2] = bx; acc[mt][nt][3] = by;
            }
#pragma unroll
        for (int kk = 0; kk < 2; kk++) {
#pragma unroll
            for (int nt = 0; nt < 8; nt++) {
                int nloc  = wN * 64 + nt * 8 + lb;
                int nodeb = wM * 32 + kk * 16 + 2 * la;
                uint32_t b0 = *(const uint32_t*)&Ts[nloc * 136 + nodeb];
                uint32_t b1 = *(const uint32_t*)&Ts[nloc * 136 + nodeb + 8];
                mma16(acc[0][nt], af[0][kk], b0, b1);
                mma16(acc[1][nt], af[1][kk], b0, b1);
            }
        }
        __syncthreads();                 // Ts reads done; Fpre overlays it

        // ---- write Fpre (pre-ReLU) and Fcur (post-ReLU) ----
#pragma unroll
        for (int mt = 0; mt < 2; mt++)
#pragma unroll
            for (int nt = 0; nt < 8; nt++) {
                int r = wM * 32 + mt * 16 + lb;
                int p = wN * 32 + nt * 4 + la;
                Fpre[r * 132 + p] =
                    pack_bf16x2(acc[mt][nt][0], acc[mt][nt][1]);
                Fpre[(r + 8) * 132 + p] =
                    pack_bf16x2(acc[mt][nt][2], acc[mt][nt][3]);
                if (l < 2) {
                    Fcur[r * 132 + p] =
                        pack_bf16x2(fmaxf(acc[mt][nt][0], 0.f),
                                    fmaxf(acc[mt][nt][1], 0.f));
                    Fcur[(r + 8) * 132 + p] =
                        pack_bf16x2(fmaxf(acc[mt][nt][2], 0.f),
                                    fmaxf(acc[mt][nt][3], 0.f));
                }
            }
        __syncthreads();

        // ---- cost: warps 0-7 mma Q@C^T; warps 8-11 del/ins dots ----
        float ca[2][4];
        int p = warp >> 2, cwm = (warp >> 1) & 1, cwn = warp & 1;
        if (warp < 8) {
#pragma unroll
            for (int t = 0; t < 2; t++)
#pragma unroll
                for (int e = 0; e < 4; e++) ca[t][e] = 0.f;
            int qr = p * 32 + cwm * 16 + lb;
#pragma unroll 4
            for (int kk = 0; kk < 128; kk += 8) {
                uint32_t a[4];
                a[0] = Fpre[qr * 132 + kk + la];
                a[1] = Fpre[(qr + 8) * 132 + kk + la];
                a[2] = Fpre[qr * 132 + kk + la + 4];
                a[3] = Fpre[(qr + 8) * 132 + kk + la + 4];
#pragma unroll
                for (int t = 0; t < 2; t++) {
                    int cr = 64 + p * 32 + cwn * 16 + t * 8 + lb;
                    uint32_t b0 = Fpre[cr * 132 + kk + la];
                    uint32_t b1 = Fpre[cr * 132 + kk + la + 4];
                    mma16(ca[t], a, b0, b1);
                }
            }
        } else if (warp < 12) {
            int rr = (warp - 8) * 32 + lane;       // 0..127
            const float* vec = (rr < 64) ? (del_p + l * FD) : (ins_p + l * FD);
            float s = 0.f;
#pragma unroll 16
            for (int p2 = 0; p2 < FP; p2++) {
                __nv_bfloat162 h = *(const __nv_bfloat162*)&Fpre[rr * 132 + p2];
                float2 f = __bfloat1622float2(h);
                s += f.x * vec[2 * p2] + f.y * vec[2 * p2 + 1];
            }
            dotS[rr] = s;
        }
        __syncthreads();
        if (warp < 8) {
            float* C = costS + (l * 2 + p) * (32 * 33);
#pragma unroll
            for (int t = 0; t < 2; t++) {
                int row = cwm * 16 + lb;
                int col = cwn * 16 + t * 8 + 2 * la;
                float dq0 = dotS[p * 32 + row], dq1 = dotS[p * 32 + row + 8];
                float ic0 = dotS[64 + p * 32 + col];
                float ic1 = dotS[64 + p * 32 + col + 1];
                C[row * 33 + col]           = fminf(-ca[t][0], -(dq0 + ic0));
                C[row * 33 + col + 1]       = fminf(-ca[t][1], -(dq0 + ic1));
                C[(row + 8) * 33 + col]     = fminf(-ca[t][2], -(dq1 + ic0));
                C[(row + 8) * 33 + col + 1] = fminf(-ca[t][3], -(dq1 + ic1));
            }
        }
        __syncthreads();
    }

    // ---- 6 LAPs in parallel (warps 0-5), Jonker-Volgenant 32x32 ----
    if (warp < 6) {
        float* C   = costS + warp * (32 * 33);
        float* su  = (float*)(dsm + W_SU)  + warp * 32;
        int* r4c   = (int*)(dsm + W_R4C)   + warp * 32;
        int* c4r   = (int*)(dsm + W_C4R)   + warp * 32;
        int* pth   = (int*)(dsm + W_PATH)  + warp * 32;
        float* mc  = (float*)(dsm + W_MC);

        su[lane] = 0.f;
        r4c[lane] = -1;
        c4r[lane] = -1;
        float v = 0.f;
        __syncwarp();

        const float FINF = __int_as_float(0x7f800000);
        for (int cur = 0; cur < SS; cur++) {
            float sh = FINF;
            bool sc = false;
            int i = cur;
            float minv = 0.f;
            int sink = -1;
            while (sink < 0) {
                float base = minv - su[i];
                if (!sc) {
                    float r = base + C[i * 33 + lane] - v;
                    if (r < sh) { sh = r; pth[lane] = i; }
                }
                unsigned key = sc ? 0xFFFFFFFFu : fkey(sh);
                unsigned mk = __reduce_min_sync(0xffffffffu, key);
                unsigned ball = __ballot_sync(0xffffffffu, key == mk);
                int mj = __ffs(ball) - 1;
                minv = __shfl_sync(0xffffffffu, sh, mj);
                if (lane == mj) sc = true;
                int r4 = r4c[mj];
                if (r4 < 0) sink = mj; else i = r4;
            }
            if (lane == 0) su[cur] += minv;
            if (sc) {
                float d = minv - sh;
                v -= d;
                if (lane != sink) su[r4c[lane]] += d;
            }
            __syncwarp();
            if (lane == 0) {
                int j = sink;
                while (true) {
                    int i2 = pth[j];
                    r4c[j] = i2;
                    int jn = c4r[i2];
                    c4r[i2] = j;
                    j = jn;
                    if (i2 == cur) break;
                }
            }
            __syncwarp();
        }
        float tot = C[r4c[lane] * 33 + lane];
#pragma unroll
        for (int o = 16; o; o >>= 1) tot += __shfl_xor_sync(0xffffffffu, tot, o);
        if (lane == 0) mc[warp] = tot;
    }
    __syncthreads();

    // ---- final scores for batches 2bb, 2bb+1 ----
    if (tid < 2) {
        const float* mc = (const float*)(dsm + W_MC);
        float s = ot_b[0];
#pragma unroll
        for (int l = 0; l < LLY; l++)
            s += (mc[l * 2 + tid] * (1.0f / 32.0f)) * ot_w[l];
        out[2 * bb + tid] = 1.f / (1.f + expf(-s));
    }
}

// ---------------- launch -----------------------------------------------------
extern "C" void kernel_launch(void* const* d_in, const int* in_sizes, int n_in,
                              void* d_out, int out_size) {
    const float* x_q   = (const float*)d_in[0];
    const float* x_c   = (const float*)d_in[1];
    const float* W0    = (const float*)d_in[2];
    const float* b0    = (const float*)d_in[3];
    const float* W1    = (const float*)d_in[4];
    const float* b1    = (const float*)d_in[5];
    const float* W2    = (const float*)d_in[6];
    const float* b2    = (const float*)d_in[7];
    const float* del_p = (const float*)d_in[8];
    const float* ins_p = (const float*)d_in[9];
    const float* ot_w  = (const float*)d_in[10];
    const float* ot_b  = (const float*)d_in[11];
    const int*   eq    = (const int*)d_in[12];
    const int*   ec    = (const int*)d_in[13];
    float* out = (float*)d_out;

    cudaFuncSetAttribute(mega_kernel,
                         cudaFuncAttributeMaxDynamicSharedMemorySize,
                         DSM_BYTES);

    convert_kernel<<<4736, 256>>>(x_q, x_c, W0, W1, W2);
    cnt_kernel<<<512, 256>>>(eq, ec);
    adj_prep_kernel<<<NG, 32>>>();
    mega_kernel<<<128, 512, DSM_BYTES>>>(del_p, ins_p, b0, b1, b2,
                                         ot_w, ot_b, out);
}

// round 15
// speedup vs baseline: 1.0976x; 1.0115x over previous
#include <cuda_runtime.h>
#include <math.h>
#include <stdint.h>
#include <cuda_bf16.h>

#define NN   8192      // nodes per graph side (B*S)
#define FD   256       // hidden dim
#define FIN0 512       // input dim
#define NE   65536     // directed edges per graph (already symmetric)
#define NB   256       // batch
#define SS   32        // nodes per graph
#define LLY  3         // layers
#define NG   (2 * NB)  // total graphs (q side then c side)
#define XW   (FIN0 / 2)// bf16 pairs per input row (256)
#define FP   (FD / 2)  // bf16 pairs per feature row (128)

// ---- per-block dynamic smem layout (uint32 word offsets) --------------------
// Region 0 is time-shared: GEMM staging (Bs+As) -> Ts -> Fpre, all phase-disjoint.
#define W_BS    0                        // Bs[2][16][264] = 8448
#define W_AS    (2 * 16 * 264)           // As[2][64][20] = 2560 -> 11008
#define REGION0 (W_AS + 2 * 64 * 20)     // 11008 words (>= Ts 9216, Fpre 8448)
#define W_FCUR  REGION0                  // Fcur[64][132] = 8448
#define W_COST  (W_FCUR + 64 * 132)      // cost[3][32*33] = 3168
#define W_DOT   (W_COST + 3 * 32 * 33)   // dot[64]
#define W_SU    (W_DOT + 64)             // 3*32
#define W_R4C   (W_SU + 96)
#define W_C4R   (W_R4C + 96)
#define W_PATH  (W_C4R + 96)
#define W_MC    (W_PATH + 96)
#define W_TOT   (W_MC + 4)               // 23076 words
#define DSM_BYTES (W_TOT * 4)            // 92304 bytes -> 2 blocks/SM

// ---------------- scratch (static device globals; no allocation) -------------
__device__ int      g_adjcnt[NG * SS * SS];
__device__ uint32_t g_adjP[NG * SS * 16];            // normalized adjacency bf16x2
__device__ uint32_t g_xb[2 * NN * XW];               // input x as bf16 pairs
__device__ uint32_t g_wb0[(FIN0 / 2) * FD];          // W packed (k,k+1) pairs
__device__ uint32_t g_wb1[(FD / 2) * FD];
__device__ uint32_t g_wb2[(FD / 2) * FD];

// ---------------- helpers ----------------------------------------------------
__device__ __forceinline__ uint32_t pack_bf16x2(float lo, float hi) {
    uint32_t r;
    asm("cvt.rn.bf16x2.f32 %0, %1, %2;" : "=r"(r) : "f"(hi), "f"(lo));
    return r;
}
__device__ __forceinline__ void mma16(float* c, const uint32_t* a,
                                      uint32_t b0, uint32_t b1) {
    asm volatile("mma.sync.aligned.m16n8k16.row.col.f32.bf16.bf16.f32 "
                 "{%0,%1,%2,%3}, {%4,%5,%6,%7}, {%8,%9}, {%0,%1,%2,%3};"
                 : "+f"(c[0]), "+f"(c[1]), "+f"(c[2]), "+f"(c[3])
                 : "r"(a[0]), "r"(a[1]), "r"(a[2]), "r"(a[3]),
                   "r"(b0), "r"(b1));
}
__device__ __forceinline__ unsigned fkey(float f) {
    unsigned b = __float_as_uint(f);
    return (b & 0x80000000u) ? ~b : (b | 0x80000000u);
}

// ---------------- operand conversion + adjcnt zeroing (once) -----------------
__global__ void convert_kernel(const float* __restrict__ xq,
                               const float* __restrict__ xc,
                               const float* __restrict__ W0,
                               const float* __restrict__ W1,
                               const float* __restrict__ W2) {
    int t = blockIdx.x * blockDim.x + threadIdx.x;   // quad index
    const int NXQ = 2 * NN * XW / 4;                 // 1,048,576 x-quads
    if (t < NXQ) {
        int row = t >> 6;
        int q   = t & 63;
        const float* src = (row < NN) ? (xq + (size_t)row * FIN0 + q * 8)
                                      : (xc + (size_t)(row - NN) * FIN0 + q * 8);
        float4 v0 = *(const float4*)src;
        float4 v1 = *(const float4*)(src + 4);
        uint4 o;
        o.x = pack_bf16x2(v0.x, v0.y); o.y = pack_bf16x2(v0.z, v0.w);
        o.z = pack_bf16x2(v1.x, v1.y); o.w = pack_bf16x2(v1.z, v1.w);
        *(uint4*)&g_xb[(size_t)row * XW + q * 4] = o;
        return;
    }
    int u = t - NXQ;
    if (u < 32768) {                                 // weight packing
        const float* W; uint32_t* Wo; int nq;
        if (u < 16384)      { W = W0; Wo = g_wb0; nq = u; }
        else if (u < 24576) { W = W1; Wo = g_wb1; nq = u - 16384; }
        else                { W = W2; Wo = g_wb2; nq = u - 24576; }
        int kp = nq >> 6;
        int n4 = (nq & 63) * 4;
        float4 a = *(const float4*)&W[(size_t)(2 * kp) * FD + n4];
        float4 b = *(const float4*)&W[(size_t)(2 * kp + 1) * FD + n4];
        uint4 o;
        o.x = pack_bf16x2(a.x, b.x); o.y = pack_bf16x2(a.y, b.y);
        o.z = pack_bf16x2(a.z, b.z); o.w = pack_bf16x2(a.w, b.w);
        *(uint4*)&Wo[(size_t)kp * FD + n4] = o;
        return;
    }
    int z = u - 32768;                               // zero g_adjcnt
    if (z < NG * SS * SS / 4)
        *(uint4*)&g_adjcnt[z * 4] = make_uint4(0, 0, 0, 0);
}

// ---------------- dense adjacency counts -------------------------------------
__global__ void cnt_kernel(const int* __restrict__ eq,
                           const int* __restrict__ ec) {
    int t = blockIdx.x * blockDim.x + threadIdx.x;   // 2*NE
    int g = (t < NE) ? 0 : 1;
    int e = t - g * NE;
    const int* ei = g ? ec : eq;
    int src = ei[e];
    int dst = ei[NE + e];
    int graph = g * NB + (dst >> 5);
    atomicAdd(&g_adjcnt[graph * (SS * SS) + (dst & 31) * SS + (src & 31)], 1);
}

__global__ void adj_prep_kernel() {       // grid NG, block 32
    int g = blockIdx.x;
    int d = threadIdx.x;
    __shared__ float sdinv[SS];
    const int* cnt = g_adjcnt + g * (SS * SS) + d * SS;
    int deg = 1;                           // self loop
#pragma unroll
    for (int s = 0; s < SS; s++) deg += cnt[s];
    float di = rsqrtf((float)deg);
    sdinv[d] = di;
    __syncwarp();
    uint32_t* outp = g_adjP + g * (SS * 16) + d * 16;
#pragma unroll
    for (int p = 0; p < 16; p++) {
        float a0 = cnt[2 * p]     * di * sdinv[2 * p];
        float a1 = cnt[2 * p + 1] * di * sdinv[2 * p + 1];
        if (d == 2 * p)     a0 += di * di;
        if (d == 2 * p + 1) a1 += di * di;
        outp[p] = pack_bf16x2(a0, a1);
    }
}

// ---------------- MEGA kernel: one batch per block ---------------------------
// Block bb owns q-graph bb (rows 0-31) and c-graph bb (rows 32-63).
// All 3 GCN layers + 3 cost mats + 3 LAPs + score run in shared memory.
__global__ void __launch_bounds__(256, 2)
mega_kernel(const float* __restrict__ del_p, const float* __restrict__ ins_p,
            const float* __restrict__ bias0, const float* __restrict__ bias1,
            const float* __restrict__ bias2,
            const float* __restrict__ ot_w, const float* __restrict__ ot_b,
            float* __restrict__ out) {
    extern __shared__ __align__(16) uint32_t dsm[];
    const int bb   = blockIdx.x;          // 0..255 (batch)
    const int tid  = threadIdx.x;
    const int lane = tid & 31;
    const int warp = tid >> 5;            // 0..7
    const int wM = warp >> 2, wN = warp & 3;   // 2x4 warp grid, 32x64 tiles
    const int la = lane & 3, lb = lane >> 2;

    uint32_t* Bs   = dsm + W_BS;                         // staged W
    uint32_t* As   = dsm + W_AS;                         // staged A (layer 0)
    __nv_bfloat16* Ts = (__nv_bfloat16*)dsm;             // [256][72] overlay
    uint32_t* Fpre = dsm;                                // [64][132] overlay
    uint32_t* Fcur = dsm + W_FCUR;                       // [64][132] post-ReLU
    float* costS = (float*)(dsm + W_COST);               // [3][32*33]
    float* dotS  = (float*)(dsm + W_DOT);                // [64]

    // loader mappings
    const int aR = tid >> 2, aW = (tid & 3) * 4;                  // A: 1 uint4
    const int grA = (aR < 32) ? (bb * SS + aR) : (NN + bb * SS + aR - 32);
    const uint32_t* aSrc = g_xb + (size_t)grA * XW + aW;
    int bkp[4], bw[4];                                            // B: 4 uint4
#pragma unroll
    for (int j = 0; j < 4; j++) {
        bkp[j] = (tid + j * 256) >> 6;
        bw[j]  = ((tid + j * 256) & 63) * 4;
    }

    for (int l = 0; l < LLY; l++) {
        const uint32_t* Wb = (l == 0) ? g_wb0 : ((l == 1) ? g_wb1 : g_wb2);
        const float* bias  = (l == 0) ? bias0 : ((l == 1) ? bias1 : bias2);
        const int nIt = (l == 0) ? 16 : 8;

        float acc[2][8][4];
#pragma unroll
        for (int mt = 0; mt < 2; mt++)
#pragma unroll
            for (int nt = 0; nt < 8; nt++)
#pragma unroll
                for (int e = 0; e < 4; e++) acc[mt][nt][e] = 0.f;

        // prefetch stage 0
        uint4 rb[4], ra;
#pragma unroll
        for (int j = 0; j < 4; j++)
            rb[j] = *(const uint4*)(Wb + (size_t)bkp[j] * FD + bw[j]);
        if (l == 0) ra = *(const uint4*)(aSrc);

        for (int it = 0; it < nIt; it++) {
            const int buf = it & 1;
#pragma unroll
            for (int j = 0; j < 4; j++)
                *(uint4*)&Bs[buf * 4224 + bkp[j] * 264 + bw[j]] = rb[j];
            if (l == 0)
                *(uint4*)&As[buf * 1280 + aR * 20 + aW] = ra;
            __syncthreads();             // single barrier per stage

            if (it + 1 < nIt) {          // prefetch overlaps compute
                int kw = (it + 1) * 16;
#pragma unroll
                for (int j = 0; j < 4; j++)
                    rb[j] = *(const uint4*)(Wb + (size_t)(kw + bkp[j]) * FD + bw[j]);
                if (l == 0) ra = *(const uint4*)(aSrc + kw);
            }

            const uint32_t* Asb = As + buf * 1280;
            const uint32_t* Bsb = Bs + buf * 4224;
#pragma unroll
            for (int kk2 = 0; kk2 < 16; kk2 += 8) {
                uint32_t a[2][4];
#pragma unroll
                for (int mt = 0; mt < 2; mt++) {
                    int r = wM * 32 + mt * 16 + lb;
                    if (l == 0) {
                        a[mt][0] = Asb[r * 20 + kk2 + la];
                        a[mt][1] = Asb[(r + 8) * 20 + kk2 + la];
                        a[mt][2] = Asb[r * 20 + kk2 + la + 4];
                        a[mt][3] = Asb[(r + 8) * 20 + kk2 + la + 4];
                    } else {
                        int kka = it * 16 + kk2 + la;
                        a[mt][0] = Fcur[r * 132 + kka];
                        a[mt][1] = Fcur[(r + 8) * 132 + kka];
                        a[mt][2] = Fcur[r * 132 + kka + 4];
                        a[mt][3] = Fcur[(r + 8) * 132 + kka + 4];
                    }
                }
#pragma unroll
                for (int nt = 0; nt < 8; nt++) {
                    int c = wN * 64 + nt * 8 + lb;
                    uint32_t b0 = Bsb[(kk2 + la) * 264 + c];
                    uint32_t b1 = Bsb[(kk2 + 4 + la) * 264 + c];
                    mma16(acc[0][nt], a[0], b0, b1);
                    mma16(acc[1][nt], a[1], b0, b1);
                }
            }
        }
        __syncthreads();                 // GEMM reads done; Ts overlays Bs/As

        // ---- stage T transposed to smem (bf16 Ts[col][node], stride 72) ----
#pragma unroll
        for (int mt = 0; mt < 2; mt++)
#pragma unroll
            for (int nt = 0; nt < 8; nt++) {
                int r = wM * 32 + mt * 16 + lb;
                int c = wN * 64 + nt * 8 + la * 2;
                Ts[c * 72 + r]           = __float2bfloat16(acc[mt][nt][0]);
                Ts[(c + 1) * 72 + r]     = __float2bfloat16(acc[mt][nt][1]);
                Ts[c * 72 + r + 8]       = __float2bfloat16(acc[mt][nt][2]);
                Ts[(c + 1) * 72 + r + 8] = __float2bfloat16(acc[mt][nt][3]);
            }
        __syncthreads();

        // ---- aggregation: D = Ahat(graph) @ T + bias ----
        const int gidx = (wM == 0) ? bb : (NB + bb);
        const uint32_t* AhP = g_adjP + gidx * 512;
        uint32_t af[2][2][4];
#pragma unroll
        for (int mt = 0; mt < 2; mt++)
#pragma unroll
            for (int kk = 0; kk < 2; kk++) {
                af[mt][kk][0] = AhP[(mt * 16 + lb) * 16 + kk * 8 + la];
                af[mt][kk][1] = AhP[(mt * 16 + lb + 8) * 16 + kk * 8 + la];
                af[mt][kk][2] = AhP[(mt * 16 + lb) * 16 + kk * 8 + la + 4];
                af[mt][kk][3] = AhP[(mt * 16 + lb + 8) * 16 + kk * 8 + la + 4];
            }
#pragma unroll
        for (int mt = 0; mt < 2; mt++)
#pragma unroll
            for (int nt = 0; nt < 8; nt++) {
                int c = wN * 64 + nt * 8 + la * 2;
                float bx = bias[c], by = bias[c + 1];
                acc[mt][nt][0] = bx; acc[mt][nt][1] = by;
                acc[mt][nt][2] = bx; acc[mt][nt][3] = by;
            }
#pragma unroll
        for (int kk = 0; kk < 2; kk++) {
#pragma unroll
            for (int nt = 0; nt < 8; nt++) {
                int nloc  = wN * 64 + nt * 8 + lb;
                int nodeb = wM * 32 + kk * 16 + 2 * la;
                uint32_t b0 = *(const uint32_t*)&Ts[nloc * 72 + nodeb];
                uint32_t b1 = *(const uint32_t*)&Ts[nloc * 72 + nodeb + 8];
                mma16(acc[0][nt], af[0][kk], b0, b1);
                mma16(acc[1][nt], af[1][kk], b0, b1);
            }
        }
        __syncthreads();                 // Ts reads done; Fpre overlays it

        // ---- write Fpre (pre-ReLU) and Fcur (post-ReLU) ----
#pragma unroll
        for (int mt = 0; mt < 2; mt++)
#pragma unroll
            for (int nt = 0; nt < 8; nt++) {
                int r = wM * 32 + mt * 16 + lb;
                int p = wN * 32 + nt * 4 + la;
                Fpre[r * 132 + p] =
                    pack_bf16x2(acc[mt][nt][0], acc[mt][nt][1]);
                Fpre[(r + 8) * 132 + p] =
                    pack_bf16x2(acc[mt][nt][2], acc[mt][nt][3]);
                if (l < 2) {
                    Fcur[r * 132 + p] =
                        pack_bf16x2(fmaxf(acc[mt][nt][0], 0.f),
                                    fmaxf(acc[mt][nt][1], 0.f));
                    Fcur[(r + 8) * 132 + p] =
                        pack_bf16x2(fmaxf(acc[mt][nt][2], 0.f),
                                    fmaxf(acc[mt][nt][3], 0.f));
                }
            }
        __syncthreads();

        // ---- cost: warps 0-3 mma Q@C^T; warps 4-5 del/ins dots ----
        float ca[2][4];
        const int cwm = (warp >> 1) & 1, cwn = warp & 1;
        if (warp < 4) {
#pragma unroll
            for (int t = 0; t < 2; t++)
#pragma unroll
                for (int e = 0; e < 4; e++) ca[t][e] = 0.f;
            int qr = cwm * 16 + lb;
#pragma unroll 4
            for (int kk = 0; kk < 128; kk += 8) {
                uint32_t a[4];
                a[0] = Fpre[qr * 132 + kk + la];
                a[1] = Fpre[(qr + 8) * 132 + kk + la];
                a[2] = Fpre[qr * 132 + kk + la + 4];
                a[3] = Fpre[(qr + 8) * 132 + kk + la + 4];
#pragma unroll
                for (int t = 0; t < 2; t++) {
                    int cr = 32 + cwn * 16 + t * 8 + lb;
                    uint32_t b0 = Fpre[cr * 132 + kk + la];
                    uint32_t b1 = Fpre[cr * 132 + kk + la + 4];
                    mma16(ca[t], a, b0, b1);
                }
            }
        } else if (warp < 6) {
            int rr = (warp - 4) * 32 + lane;       // 0..63
            const float* vec = (rr < 32) ? (del_p + l * FD) : (ins_p + l * FD);
            float s = 0.f;
#pragma unroll 16
            for (int p2 = 0; p2 < FP; p2++) {
                __nv_bfloat162 h = *(const __nv_bfloat162*)&Fpre[rr * 132 + p2];
                float2 f = __bfloat1622float2(h);
                s += f.x * vec[2 * p2] + f.y * vec[2 * p2 + 1];
            }
            dotS[rr] = s;
        }
        __syncthreads();
        if (warp < 4) {
            float* C = costS + l * (32 * 33);
#pragma unroll
            for (int t = 0; t < 2; t++) {
                int row = cwm * 16 + lb;
                int col = cwn * 16 + t * 8 + 2 * la;
                float dq0 = dotS[row], dq1 = dotS[row + 8];
                float ic0 = dotS[32 + col], ic1 = dotS[32 + col + 1];
                C[row * 33 + col]           = fminf(-ca[t][0], -(dq0 + ic0));
                C[row * 33 + col + 1]       = fminf(-ca[t][1], -(dq0 + ic1));
                C[(row + 8) * 33 + col]     = fminf(-ca[t][2], -(dq1 + ic0));
                C[(row + 8) * 33 + col + 1] = fminf(-ca[t][3], -(dq1 + ic1));
            }
        }
        __syncthreads();
    }

    // ---- 3 LAPs in parallel (warps 0-2), Jonker-Volgenant 32x32 ----
    if (warp < 3) {
        float* C   = costS + warp * (32 * 33);
        float* su  = (float*)(dsm + W_SU)  + warp * 32;
        int* r4c   = (int*)(dsm + W_R4C)   + warp * 32;
        int* c4r   = (int*)(dsm + W_C4R)   + warp * 32;
        int* pth   = (int*)(dsm + W_PATH)  + warp * 32;
        float* mc  = (float*)(dsm + W_MC);

        su[lane] = 0.f;
        r4c[lane] = -1;
        c4r[lane] = -1;
        float v = 0.f;
        __syncwarp();

        const float FINF = __int_as_float(0x7f800000);
        for (int cur = 0; cur < SS; cur++) {
            float sh = FINF;
            bool sc = false;
            int i = cur;
            float minv = 0.f;
            int sink = -1;
            while (sink < 0) {
                float base = minv - su[i];
                if (!sc) {
                    float r = base + C[i * 33 + lane] - v;
                    if (r < sh) { sh = r; pth[lane] = i; }
                }
                unsigned key = sc ? 0xFFFFFFFFu : fkey(sh);
                unsigned mk = __reduce_min_sync(0xffffffffu, key);
                unsigned ball = __ballot_sync(0xffffffffu, key == mk);
                int mj = __ffs(ball) - 1;
                minv = __shfl_sync(0xffffffffu, sh, mj);
                if (lane == mj) sc = true;
                int r4 = r4c[mj];
                if (r4 < 0) sink = mj; else i = r4;
            }
            if (lane == 0) su[cur] += minv;
            if (sc) {
                float d = minv - sh;
                v -= d;
                if (lane != sink) su[r4c[lane]] += d;
            }
            __syncwarp();
            if (lane == 0) {
                int j = sink;
                while (true) {
                    int i2 = pth[j];
                    r4c[j] = i2;
                    int jn = c4r[i2];
                    c4r[i2] = j;
                    j = jn;
                    if (i2 == cur) break;
                }
            }
            __syncwarp();
        }
        float tot = C[r4c[lane] * 33 + lane];
#pragma unroll
        for (int o = 16; o; o >>= 1) tot += __shfl_xor_sync(0xffffffffu, tot, o);
        if (lane == 0) mc[warp] = tot;
    }
    __syncthreads();

    // ---- final score ----
    if (tid == 0) {
        const float* mc = (const float*)(dsm + W_MC);
        float s = ot_b[0];
#pragma unroll
        for (int l = 0; l < LLY; l++)
            s += (mc[l] * (1.0f / 32.0f)) * ot_w[l];
        out[bb] = 1.f / (1.f + expf(-s));
    }
}

// ---------------- launch -----------------------------------------------------
extern "C" void kernel_launch(void* const* d_in, const int* in_sizes, int n_in,
                              void* d_out, int out_size) {
    const float* x_q   = (const float*)d_in[0];
    const float* x_c   = (const float*)d_in[1];
    const float* W0    = (const float*)d_in[2];
    const float* b0    = (const float*)d_in[3];
    const float* W1    = (const float*)d_in[4];
    const float* b1    = (const float*)d_in[5];
    const float* W2    = (const float*)d_in[6];
    const float* b2    = (const float*)d_in[7];
    const float* del_p = (const float*)d_in[8];
    const float* ins_p = (const float*)d_in[9];
    const float* ot_w  = (const float*)d_in[10];
    const float* ot_b  = (const float*)d_in[11];
    const int*   eq    = (const int*)d_in[12];
    const int*   ec    = (const int*)d_in[13];
    float* out = (float*)d_out;

    cudaFuncSetAttribute(mega_kernel,
                         cudaFuncAttributeMaxDynamicSharedMemorySize,
                         DSM_BYTES);

    convert_kernel<<<4736, 256>>>(x_q, x_c, W0, W1, W2);
    cnt_kernel<<<512, 256>>>(eq, ec);
    adj_prep_kernel<<<NG, 32>>>();
    mega_kernel<<<NB, 256, DSM_BYTES>>>(del_p, ins_p, b0, b1, b2,
                                        ot_w, ot_b, out);
}